// round 6
// baseline (speedup 1.0000x reference)
#include <cuda_runtime.h>
#include <cstdint>
#include <math.h>

#define S_LEN  2048
#define D_DIM  1536
#define N_HEADS 24
#define HD      64
#define WND    512

// Scratch (device globals: no allocations allowed)
__device__ float g_Q[S_LEN * D_DIM];
__device__ float g_K[S_LEN * D_DIM];
__device__ float g_V[S_LEN * D_DIM];
__device__ int   g_smask[S_LEN];

// ---------------------------------------------------------------------------
// spike_mask dtype detection + normalization (scan bounded to 2048 bytes,
// valid under every dtype hypothesis: bool/u8, int32, float32, bf16).
// ---------------------------------------------------------------------------
__global__ void prep_mask_kernel(const unsigned char* __restrict__ raw) {
    __shared__ int fgt1, foneoff, f3f1;
    int tid = threadIdx.x;
    if (tid == 0) { fgt1 = 0; foneoff = 0; f3f1 = 0; }
    __syncthreads();
    int lgt1 = 0, loneoff = 0, l3f1 = 0;
    for (int i = tid; i < S_LEN; i += blockDim.x) {
        unsigned char b = raw[i];
        if (b > 1) lgt1 = 1;
        if (b == 1 && (i & 3)) loneoff = 1;
        if (b == 0x3F && ((i & 3) == 1)) l3f1 = 1;
    }
    if (lgt1)    atomicOr(&fgt1, 1);
    if (loneoff) atomicOr(&foneoff, 1);
    if (l3f1)    atomicOr(&f3f1, 1);
    __syncthreads();
    // mode: 0=bool/u8, 1=int32, 2=float32, 3=bf16
    int mode = fgt1 ? (f3f1 ? 3 : 2) : (foneoff ? 0 : 1);
    for (int i = tid; i < S_LEN; i += blockDim.x) {
        int v;
        if (mode == 0)      v = (raw[i] != 0);
        else if (mode == 1) v = (((const int*)raw)[i] != 0);
        else if (mode == 2) v = (((const float*)raw)[i] != 0.0f);
        else                v = (((const unsigned short*)raw)[i] != 0);
        g_smask[i] = v;
    }
}

// ---------------------------------------------------------------------------
// Fused QKV projection: C[s,e] = sum_d x[s,d] * W[e,d]; RoPE fused for Q,K.
// BM=128, BN=64, BK=16, 256 threads, 8x4 microtile.
// ---------------------------------------------------------------------------
__global__ __launch_bounds__(256) void qkv_gemm_kernel(
    const float* __restrict__ x,
    const float* __restrict__ Wq,
    const float* __restrict__ Wk,
    const float* __restrict__ Wv)
{
    __shared__ float As[16][132];
    __shared__ float Bs[16][68];
    int bz = blockIdx.z;
    const float* Wm  = (bz == 0) ? Wq : (bz == 1) ? Wk : Wv;
    float*       outp = (bz == 0) ? g_Q : (bz == 1) ? g_K : g_V;
    int s0 = blockIdx.x * 128;
    int n0 = blockIdx.y * 64;
    int tid = threadIdx.x;
    int tx = tid & 15, ty = tid >> 4;
    int lm = tid >> 2, lk = (tid & 3) << 2;

    float acc[8][4];
    #pragma unroll
    for (int i = 0; i < 8; i++)
        #pragma unroll
        for (int j = 0; j < 4; j++) acc[i][j] = 0.f;

    const float* ap0 = x  + (size_t)(s0 + lm) * D_DIM + lk;
    const float* ap1 = ap0 + (size_t)64 * D_DIM;
    const float* bp  = Wm + (size_t)(n0 + lm) * D_DIM + lk;

    for (int k0 = 0; k0 < D_DIM; k0 += 16) {
        float4 a0 = *(const float4*)(ap0 + k0);
        float4 a1 = *(const float4*)(ap1 + k0);
        float4 b0 = *(const float4*)(bp  + k0);
        As[lk+0][lm]    = a0.x; As[lk+1][lm]    = a0.y; As[lk+2][lm]    = a0.z; As[lk+3][lm]    = a0.w;
        As[lk+0][lm+64] = a1.x; As[lk+1][lm+64] = a1.y; As[lk+2][lm+64] = a1.z; As[lk+3][lm+64] = a1.w;
        Bs[lk+0][lm]    = b0.x; Bs[lk+1][lm]    = b0.y; Bs[lk+2][lm]    = b0.z; Bs[lk+3][lm]    = b0.w;
        __syncthreads();
        #pragma unroll
        for (int k = 0; k < 16; k++) {
            float4 av0 = *(const float4*)&As[k][ty*8];
            float4 av1 = *(const float4*)&As[k][ty*8+4];
            float4 bv  = *(const float4*)&Bs[k][tx*4];
            float a[8] = {av0.x, av0.y, av0.z, av0.w, av1.x, av1.y, av1.z, av1.w};
            float b[4] = {bv.x, bv.y, bv.z, bv.w};
            #pragma unroll
            for (int i = 0; i < 8; i++)
                #pragma unroll
                for (int j = 0; j < 4; j++)
                    acc[i][j] = fmaf(a[i], b[j], acc[i][j]);
        }
        __syncthreads();
    }

    if (bz < 2) {
        // RoPE epilogue: angle(s,c) = s * 10000^(-(c%32)/32); partner = col^32
        float invf[4];
        #pragma unroll
        for (int j = 0; j < 4; j++) {
            int jj = (tx * 4 + j) & 31;
            invf[j] = (float)exp(-(double)jj * 0.28782313662425575); // ln(1e4)/32
        }
        #pragma unroll
        for (int i = 0; i < 8; i++) {
            int s = s0 + ty * 8 + i;
            float sn[4], cs[4];
            #pragma unroll
            for (int j = 0; j < 4; j++) sincosf((float)s * invf[j], &sn[j], &cs[j]);
            #pragma unroll
            for (int j = 0; j < 4; j++) {
                float v = acc[i][j];
                float partner = __shfl_xor_sync(0xffffffffu, v, 8); // lane tx^8 -> col^32
                int c = tx * 4 + j;
                float rot = (c < 32) ? -partner : partner;
                outp[(size_t)s * D_DIM + n0 + c] = fmaf(v, cs[j], rot * sn[j]);
            }
        }
    } else {
        #pragma unroll
        for (int i = 0; i < 8; i++) {
            int s = s0 + ty * 8 + i;
            float4 o4 = make_float4(acc[i][0], acc[i][1], acc[i][2], acc[i][3]);
            *(float4*)&outp[(size_t)s * D_DIM + n0 + tx * 4] = o4;
        }
    }
}

// ---------------------------------------------------------------------------
// Flash-style windowed attention. Block = (64-query tile, head).
// Tile loaders cover all 64 dims (each thread loads 4 float4s per tile).
// ---------------------------------------------------------------------------
__global__ __launch_bounds__(256) void attn_kernel(float* __restrict__ out) {
    extern __shared__ float smem[];
    float (*Qs)[68] = (float (*)[68])(smem);               // [d][q]
    float (*Ks)[68] = (float (*)[68])(smem + 1 * 64 * 68); // [d][k]
    float (*Vs)[68] = (float (*)[68])(smem + 2 * 64 * 68); // [k][d]
    float (*Ps)[68] = (float (*)[68])(smem + 3 * 64 * 68); // [q][k]
    int* smk = (int*)(smem + 4 * 64 * 68);

    int q0 = blockIdx.x * 64;
    int h  = blockIdx.y;
    int tid = threadIdx.x;
    int tx = tid & 15, ty = tid >> 4;
    int row   = tid >> 2;        // 0..63
    int cbase = (tid & 3) << 4;  // 0,16,32,48

    {   // load Q tile transposed: Qs[d][q], full 64 dims
        const float* qp = g_Q + (size_t)(q0 + row) * D_DIM + h * HD + cbase;
        #pragma unroll
        for (int t = 0; t < 4; t++) {
            float4 qv = *(const float4*)(qp + t * 4);
            int d = cbase + t * 4;
            Qs[d+0][row] = qv.x; Qs[d+1][row] = qv.y;
            Qs[d+2][row] = qv.z; Qs[d+3][row] = qv.w;
        }
    }

    float m_i[4], l_i[4], acc[4][4];
    #pragma unroll
    for (int i = 0; i < 4; i++) {
        m_i[i] = -1e30f; l_i[i] = 0.f;
        #pragma unroll
        for (int j = 0; j < 4; j++) acc[i][j] = 0.f;
    }

    int bx = blockIdx.x;
    int tlo = (bx > 8) ? (bx - 8) : 0;    // first window tile
    int nanchor = (tlo > 0) ? 1 : 0;
    int ntiles = nanchor + (bx - tlo + 1);

    for (int it = 0; it < ntiles; it++) {
        bool anchorOnly = (nanchor && it == 0);
        int kt = anchorOnly ? 0 : (tlo + it - nanchor);
        int k0 = kt * 64;
        __syncthreads();  // previous tile's PV/Ps reads complete
        {
            const float* kp = g_K + (size_t)(k0 + row) * D_DIM + h * HD + cbase;
            const float* vp = g_V + (size_t)(k0 + row) * D_DIM + h * HD + cbase;
            #pragma unroll
            for (int t = 0; t < 4; t++) {
                float4 kv = *(const float4*)(kp + t * 4);
                int d = cbase + t * 4;
                Ks[d+0][row] = kv.x; Ks[d+1][row] = kv.y;
                Ks[d+2][row] = kv.z; Ks[d+3][row] = kv.w;
                *(float4*)&Vs[row][d] = *(const float4*)(vp + t * 4);
            }
            if (tid < 64) smk[tid] = g_smask[k0 + tid];
        }
        __syncthreads();

        // scores: sc[i][j] = Q[q]·K[k]
        float sc[4][4];
        #pragma unroll
        for (int i = 0; i < 4; i++)
            #pragma unroll
            for (int j = 0; j < 4; j++) sc[i][j] = 0.f;
        #pragma unroll
        for (int d = 0; d < 64; d++) {
            float4 qq = *(const float4*)&Qs[d][ty * 4];
            float4 kk = *(const float4*)&Ks[d][tx * 4];
            float qa[4] = {qq.x, qq.y, qq.z, qq.w};
            float ka[4] = {kk.x, kk.y, kk.z, kk.w};
            #pragma unroll
            for (int i = 0; i < 4; i++)
                #pragma unroll
                for (int j = 0; j < 4; j++)
                    sc[i][j] = fmaf(qa[i], ka[j], sc[i][j]);
        }

        // mask + online softmax update
        #pragma unroll
        for (int i = 0; i < 4; i++) {
            int q = q0 + ty * 4 + i;
            float sv[4];
            float mt = -1e30f;
            #pragma unroll
            for (int j = 0; j < 4; j++) {
                int k = k0 + tx * 4 + j;
                int dist = q - k;
                bool ok = (dist >= 0) && smk[tx * 4 + j] &&
                          ((k < 4) || (!anchorOnly && dist <= WND));
                float s = sc[i][j] * 0.125f;
                sv[j] = ok ? s : -1e30f;
                mt = fmaxf(mt, sv[j]);
            }
            #pragma unroll
            for (int o = 8; o > 0; o >>= 1)
                mt = fmaxf(mt, __shfl_xor_sync(0xffffffffu, mt, o));
            float mn = fmaxf(m_i[i], mt);
            float alpha = expf(m_i[i] - mn);
            m_i[i] = mn;
            float p[4], rs = 0.f;
            #pragma unroll
            for (int j = 0; j < 4; j++) {
                p[j] = (sv[j] > -1e29f) ? expf(sv[j] - mn) : 0.f;
                rs += p[j];
            }
            #pragma unroll
            for (int o = 8; o > 0; o >>= 1)
                rs += __shfl_xor_sync(0xffffffffu, rs, o);
            l_i[i] = l_i[i] * alpha + rs;
            #pragma unroll
            for (int j = 0; j < 4; j++) acc[i][j] *= alpha;
            *(float4*)&Ps[ty * 4 + i][tx * 4] = make_float4(p[0], p[1], p[2], p[3]);
        }
        __syncthreads();

        // PV: acc[q][d] += sum_k P[q][k] * V[k][d]
        #pragma unroll 4
        for (int k = 0; k < 64; k++) {
            float4 vv = *(const float4*)&Vs[k][tx * 4];
            #pragma unroll
            for (int i = 0; i < 4; i++) {
                float pw = Ps[ty * 4 + i][k];
                acc[i][0] = fmaf(pw, vv.x, acc[i][0]);
                acc[i][1] = fmaf(pw, vv.y, acc[i][1]);
                acc[i][2] = fmaf(pw, vv.z, acc[i][2]);
                acc[i][3] = fmaf(pw, vv.w, acc[i][3]);
            }
        }
    }

    // epilogue: normalize, apply query spike mask + no-key zeroing
    #pragma unroll
    for (int i = 0; i < 4; i++) {
        int q = q0 + ty * 4 + i;
        float mult = (l_i[i] > 0.f && g_smask[q]) ? (1.f / l_i[i]) : 0.f;
        float4 o4 = make_float4(acc[i][0] * mult, acc[i][1] * mult,
                                acc[i][2] * mult, acc[i][3] * mult);
        *(float4*)&out[(size_t)q * D_DIM + h * HD + tx * 4] = o4;
    }
}

// ---------------------------------------------------------------------------
extern "C" void kernel_launch(void* const* d_in, const int* in_sizes, int n_in,
                              void* d_out, int out_size) {
    const float* x          = (const float*)d_in[0];
    const unsigned char* mk = (const unsigned char*)d_in[1];
    const float* Wq         = (const float*)d_in[2];
    const float* Wk         = (const float*)d_in[3];
    const float* Wv         = (const float*)d_in[4];
    float* out = (float*)d_out;

    prep_mask_kernel<<<1, 256>>>(mk);

    dim3 gg(S_LEN / 128, D_DIM / 64, 3);
    qkv_gemm_kernel<<<gg, 256>>>(x, Wq, Wk, Wv);

    const int ATTN_SMEM = (4 * 64 * 68 + 64) * 4;  // ~70 KB
    cudaFuncSetAttribute(attn_kernel, cudaFuncAttributeMaxDynamicSharedMemorySize, ATTN_SMEM);
    attn_kernel<<<dim3(S_LEN / 64, N_HEADS), 256, ATTN_SMEM>>>(out);
}

// round 10
// speedup vs baseline: 1.4312x; 1.4312x over previous
#include <cuda_runtime.h>
#include <cstdint>
#include <math.h>

#define S_LEN  2048
#define D_DIM  1536
#define N_HEADS 24
#define HD      64
#define WND    512

// Scratch (device globals: no allocations allowed)
__device__ float g_Q[S_LEN * D_DIM];
__device__ float g_K[S_LEN * D_DIM];
__device__ float g_V[S_LEN * D_DIM];
__device__ int   g_smask[S_LEN];
__device__ int   g_sidx[S_LEN + 128];   // compacted spike positions (padded)
__device__ int   g_npad;                // padded count (multiple of 128)

// ---------------------------------------------------------------------------
// spike_mask dtype detection + normalization + spike-index compaction.
// Single block, 256 threads. Scan bounded to 2048 bytes (safe for all dtypes).
// ---------------------------------------------------------------------------
__global__ void prep_mask_kernel(const unsigned char* __restrict__ raw) {
    __shared__ int fgt1, foneoff, f3f1;
    __shared__ int scan[256];
    int tid = threadIdx.x;
    if (tid == 0) { fgt1 = 0; foneoff = 0; f3f1 = 0; }
    __syncthreads();
    int lgt1 = 0, loneoff = 0, l3f1 = 0;
    for (int i = tid; i < S_LEN; i += blockDim.x) {
        unsigned char b = raw[i];
        if (b > 1) lgt1 = 1;
        if (b == 1 && (i & 3)) loneoff = 1;
        if (b == 0x3F && ((i & 3) == 1)) l3f1 = 1;
    }
    if (lgt1)    atomicOr(&fgt1, 1);
    if (loneoff) atomicOr(&foneoff, 1);
    if (l3f1)    atomicOr(&f3f1, 1);
    __syncthreads();
    // mode: 0=bool/u8, 1=int32, 2=float32, 3=bf16
    int mode = fgt1 ? (f3f1 ? 3 : 2) : (foneoff ? 0 : 1);
    for (int i = tid; i < S_LEN; i += blockDim.x) {
        int v;
        if (mode == 0)      v = (raw[i] != 0);
        else if (mode == 1) v = (((const int*)raw)[i] != 0);
        else if (mode == 2) v = (((const float*)raw)[i] != 0.0f);
        else                v = (((const unsigned short*)raw)[i] != 0);
        g_smask[i] = v;
    }
    __syncthreads();   // make all g_smask writes visible block-wide

    // compaction: each thread owns 8 consecutive positions
    int base = tid * 8;
    int loc[8];
    int cnt = 0;
    #pragma unroll
    for (int j = 0; j < 8; j++)
        if (g_smask[base + j]) loc[cnt++] = base + j;
    scan[tid] = cnt;
    __syncthreads();
    // inclusive Hillis-Steele scan over 256 entries
    for (int off = 1; off < 256; off <<= 1) {
        int v = scan[tid];
        int add = (tid >= off) ? scan[tid - off] : 0;
        __syncthreads();
        scan[tid] = v + add;
        __syncthreads();
    }
    int total = scan[255];
    int start = scan[tid] - cnt;
    for (int j = 0; j < cnt; j++) g_sidx[start + j] = loc[j];
    int npad = ((total + 127) >> 7) << 7;
    if (npad == 0) npad = 128;
    if (tid == 0) g_npad = npad;
    __syncthreads();   // g_sidx[0] visible
    int fi = (total > 0) ? g_sidx[0] : 0;
    for (int i = total + tid; i < npad; i += 256) g_sidx[i] = fi;
}

// ---------------------------------------------------------------------------
// Fused QKV projection over GATHERED spike rows only (~half the work).
// C[s,e] = sum_d x[s,d] * W[e,d]; RoPE fused for Q,K (angles use ORIGINAL
// positions). Results scattered to original row positions in g_Q/g_K/g_V.
// BM=128 gathered rows, BN=64, BK=16, 256 threads, 8x4 microtile.
// ---------------------------------------------------------------------------
__global__ __launch_bounds__(256) void qkv_gemm_kernel(
    const float* __restrict__ x,
    const float* __restrict__ Wq,
    const float* __restrict__ Wk,
    const float* __restrict__ Wv)
{
    int s0 = blockIdx.x * 128;
    if (s0 >= g_npad) return;            // dynamic M: idle tail blocks exit

    __shared__ float As[16][132];
    __shared__ float Bs[16][68];
    int bz = blockIdx.z;
    const float* Wm  = (bz == 0) ? Wq : (bz == 1) ? Wk : Wv;
    float*       outp = (bz == 0) ? g_Q : (bz == 1) ? g_K : g_V;
    int n0 = blockIdx.y * 64;
    int tid = threadIdx.x;
    int tx = tid & 15, ty = tid >> 4;
    int lm = tid >> 2, lk = (tid & 3) << 2;

    float acc[8][4];
    #pragma unroll
    for (int i = 0; i < 8; i++)
        #pragma unroll
        for (int j = 0; j < 4; j++) acc[i][j] = 0.f;

    int r0 = g_sidx[s0 + lm];
    int r1 = g_sidx[s0 + lm + 64];
    const float* ap0 = x  + (size_t)r0 * D_DIM + lk;
    const float* ap1 = x  + (size_t)r1 * D_DIM + lk;
    const float* bp  = Wm + (size_t)(n0 + lm) * D_DIM + lk;

    for (int k0 = 0; k0 < D_DIM; k0 += 16) {
        float4 a0 = *(const float4*)(ap0 + k0);
        float4 a1 = *(const float4*)(ap1 + k0);
        float4 b0 = *(const float4*)(bp  + k0);
        As[lk+0][lm]    = a0.x; As[lk+1][lm]    = a0.y; As[lk+2][lm]    = a0.z; As[lk+3][lm]    = a0.w;
        As[lk+0][lm+64] = a1.x; As[lk+1][lm+64] = a1.y; As[lk+2][lm+64] = a1.z; As[lk+3][lm+64] = a1.w;
        Bs[lk+0][lm]    = b0.x; Bs[lk+1][lm]    = b0.y; Bs[lk+2][lm]    = b0.z; Bs[lk+3][lm]    = b0.w;
        __syncthreads();
        #pragma unroll
        for (int k = 0; k < 16; k++) {
            float4 av0 = *(const float4*)&As[k][ty*8];
            float4 av1 = *(const float4*)&As[k][ty*8+4];
            float4 bv  = *(const float4*)&Bs[k][tx*4];
            float a[8] = {av0.x, av0.y, av0.z, av0.w, av1.x, av1.y, av1.z, av1.w};
            float b[4] = {bv.x, bv.y, bv.z, bv.w};
            #pragma unroll
            for (int i = 0; i < 8; i++)
                #pragma unroll
                for (int j = 0; j < 4; j++)
                    acc[i][j] = fmaf(a[i], b[j], acc[i][j]);
        }
        __syncthreads();
    }

    if (bz < 2) {
        // RoPE epilogue: angle(s,c) = s_orig * 10000^(-(c%32)/32); partner = col^32
        float invf[4];
        #pragma unroll
        for (int j = 0; j < 4; j++) {
            int jj = (tx * 4 + j) & 31;
            invf[j] = (float)exp(-(double)jj * 0.28782313662425575); // ln(1e4)/32
        }
        #pragma unroll
        for (int i = 0; i < 8; i++) {
            int s = g_sidx[s0 + ty * 8 + i];  // original position
            float sn[4], cs[4];
            #pragma unroll
            for (int j = 0; j < 4; j++) sincosf((float)s * invf[j], &sn[j], &cs[j]);
            #pragma unroll
            for (int j = 0; j < 4; j++) {
                float v = acc[i][j];
                float partner = __shfl_xor_sync(0xffffffffu, v, 8); // lane tx^8 -> col^32
                int c = tx * 4 + j;
                float rot = (c < 32) ? -partner : partner;
                outp[(size_t)s * D_DIM + n0 + c] = fmaf(v, cs[j], rot * sn[j]);
            }
        }
    } else {
        #pragma unroll
        for (int i = 0; i < 8; i++) {
            int s = g_sidx[s0 + ty * 8 + i];
            float4 o4 = make_float4(acc[i][0], acc[i][1], acc[i][2], acc[i][3]);
            *(float4*)&outp[(size_t)s * D_DIM + n0 + tx * 4] = o4;
        }
    }
}

// ---------------------------------------------------------------------------
// Flash-style windowed attention (unchanged from the passing R6 kernel).
// Non-spike K/V rows hold stale-but-finite data; the mask removes them.
// ---------------------------------------------------------------------------
__global__ __launch_bounds__(256) void attn_kernel(float* __restrict__ out) {
    extern __shared__ float asmem[];
    float (*Qs)[68] = (float (*)[68])(asmem);
    float (*Ks)[68] = (float (*)[68])(asmem + 1 * 64 * 68);
    float (*Vs)[68] = (float (*)[68])(asmem + 2 * 64 * 68);
    float (*Ps)[68] = (float (*)[68])(asmem + 3 * 64 * 68);
    int* smk = (int*)(asmem + 4 * 64 * 68);

    int q0 = blockIdx.x * 64;
    int h  = blockIdx.y;
    int tid = threadIdx.x;
    int tx = tid & 15, ty = tid >> 4;
    int row   = tid >> 2;
    int cbase = (tid & 3) << 4;

    {
        const float* qp = g_Q + (size_t)(q0 + row) * D_DIM + h * HD + cbase;
        #pragma unroll
        for (int t = 0; t < 4; t++) {
            float4 qv = *(const float4*)(qp + t * 4);
            int d = cbase + t * 4;
            Qs[d+0][row] = qv.x; Qs[d+1][row] = qv.y;
            Qs[d+2][row] = qv.z; Qs[d+3][row] = qv.w;
        }
    }

    float m_i[4], l_i[4], acc[4][4];
    #pragma unroll
    for (int i = 0; i < 4; i++) {
        m_i[i] = -1e30f; l_i[i] = 0.f;
        #pragma unroll
        for (int j = 0; j < 4; j++) acc[i][j] = 0.f;
    }

    int bx = blockIdx.x;
    int tlo = (bx > 8) ? (bx - 8) : 0;
    int nanchor = (tlo > 0) ? 1 : 0;
    int ntiles = nanchor + (bx - tlo + 1);

    for (int it = 0; it < ntiles; it++) {
        bool anchorOnly = (nanchor && it == 0);
        int kt = anchorOnly ? 0 : (tlo + it - nanchor);
        int k0 = kt * 64;
        __syncthreads();
        {
            const float* kp = g_K + (size_t)(k0 + row) * D_DIM + h * HD + cbase;
            const float* vp = g_V + (size_t)(k0 + row) * D_DIM + h * HD + cbase;
            #pragma unroll
            for (int t = 0; t < 4; t++) {
                float4 kv = *(const float4*)(kp + t * 4);
                int d = cbase + t * 4;
                Ks[d+0][row] = kv.x; Ks[d+1][row] = kv.y;
                Ks[d+2][row] = kv.z; Ks[d+3][row] = kv.w;
                *(float4*)&Vs[row][d] = *(const float4*)(vp + t * 4);
            }
            if (tid < 64) smk[tid] = g_smask[k0 + tid];
        }
        __syncthreads();

        float sc[4][4];
        #pragma unroll
        for (int i = 0; i < 4; i++)
            #pragma unroll
            for (int j = 0; j < 4; j++) sc[i][j] = 0.f;
        #pragma unroll
        for (int d = 0; d < 64; d++) {
            float4 qq = *(const float4*)&Qs[d][ty * 4];
            float4 kk = *(const float4*)&Ks[d][tx * 4];
            float qa[4] = {qq.x, qq.y, qq.z, qq.w};
            float ka[4] = {kk.x, kk.y, kk.z, kk.w};
            #pragma unroll
            for (int i = 0; i < 4; i++)
                #pragma unroll
                for (int j = 0; j < 4; j++)
                    sc[i][j] = fmaf(qa[i], ka[j], sc[i][j]);
        }

        #pragma unroll
        for (int i = 0; i < 4; i++) {
            int q = q0 + ty * 4 + i;
            float sv[4];
            float mt = -1e30f;
            #pragma unroll
            for (int j = 0; j < 4; j++) {
                int k = k0 + tx * 4 + j;
                int dist = q - k;
                bool ok = (dist >= 0) && smk[tx * 4 + j] &&
                          ((k < 4) || (!anchorOnly && dist <= WND));
                float sx = sc[i][j] * 0.125f;
                sv[j] = ok ? sx : -1e30f;
                mt = fmaxf(mt, sv[j]);
            }
            #pragma unroll
            for (int o = 8; o > 0; o >>= 1)
                mt = fmaxf(mt, __shfl_xor_sync(0xffffffffu, mt, o));
            float mn = fmaxf(m_i[i], mt);
            float alpha = expf(m_i[i] - mn);
            m_i[i] = mn;
            float p[4], rs = 0.f;
            #pragma unroll
            for (int j = 0; j < 4; j++) {
                p[j] = (sv[j] > -1e29f) ? expf(sv[j] - mn) : 0.f;
                rs += p[j];
            }
            #pragma unroll
            for (int o = 8; o > 0; o >>= 1)
                rs += __shfl_xor_sync(0xffffffffu, rs, o);
            l_i[i] = l_i[i] * alpha + rs;
            #pragma unroll
            for (int j = 0; j < 4; j++) acc[i][j] *= alpha;
            *(float4*)&Ps[ty * 4 + i][tx * 4] = make_float4(p[0], p[1], p[2], p[3]);
        }
        __syncthreads();

        #pragma unroll 4
        for (int k = 0; k < 64; k++) {
            float4 vv = *(const float4*)&Vs[k][tx * 4];
            #pragma unroll
            for (int i = 0; i < 4; i++) {
                float pw = Ps[ty * 4 + i][k];
                acc[i][0] = fmaf(pw, vv.x, acc[i][0]);
                acc[i][1] = fmaf(pw, vv.y, acc[i][1]);
                acc[i][2] = fmaf(pw, vv.z, acc[i][2]);
                acc[i][3] = fmaf(pw, vv.w, acc[i][3]);
            }
        }
    }

    #pragma unroll
    for (int i = 0; i < 4; i++) {
        int q = q0 + ty * 4 + i;
        float mult = (l_i[i] > 0.f && g_smask[q]) ? (1.f / l_i[i]) : 0.f;
        float4 o4 = make_float4(acc[i][0] * mult, acc[i][1] * mult,
                                acc[i][2] * mult, acc[i][3] * mult);
        *(float4*)&out[(size_t)q * D_DIM + h * HD + tx * 4] = o4;
    }
}

// ---------------------------------------------------------------------------
extern "C" void kernel_launch(void* const* d_in, const int* in_sizes, int n_in,
                              void* d_out, int out_size) {
    const float* x          = (const float*)d_in[0];
    const unsigned char* mk = (const unsigned char*)d_in[1];
    const float* Wq         = (const float*)d_in[2];
    const float* Wk         = (const float*)d_in[3];
    const float* Wv         = (const float*)d_in[4];
    float* out = (float*)d_out;

    prep_mask_kernel<<<1, 256>>>(mk);

    // worst-case M tiles (2048/128 = 16); tail blocks exit on g_npad
    dim3 gg(16, D_DIM / 64, 3);
    qkv_gemm_kernel<<<gg, 256>>>(x, Wq, Wk, Wv);

    const int ATTN_SMEM = (4 * 64 * 68 + 64) * 4;  // ~70 KB
    cudaFuncSetAttribute(attn_kernel, cudaFuncAttributeMaxDynamicSharedMemorySize, ATTN_SMEM);
    attn_kernel<<<dim3(S_LEN / 64, N_HEADS), 256, ATTN_SMEM>>>(out);
}

// round 11
// speedup vs baseline: 2.0835x; 1.4558x over previous
#include <cuda_runtime.h>
#include <cuda_bf16.h>
#include <cstdint>
#include <math.h>

#define S_LEN  2048
#define D_DIM  1536
#define N_HEADS 24
#define HD      64
#define WND    512

// Scratch (device globals: no allocations allowed)
__device__ float g_Q[S_LEN * D_DIM];
__device__ float g_K[S_LEN * D_DIM];
__device__ float g_V[S_LEN * D_DIM];
__device__ int   g_smask[S_LEN];
__device__ int   g_sidx[S_LEN + 128];
__device__ int   g_npad;

// ---------------------------------------------------------------------------
// spike_mask dtype detection + normalization + spike-index compaction.
// ---------------------------------------------------------------------------
__global__ void prep_mask_kernel(const unsigned char* __restrict__ raw) {
    __shared__ int fgt1, foneoff, f3f1;
    __shared__ int scan[256];
    int tid = threadIdx.x;
    if (tid == 0) { fgt1 = 0; foneoff = 0; f3f1 = 0; }
    __syncthreads();
    int lgt1 = 0, loneoff = 0, l3f1 = 0;
    for (int i = tid; i < S_LEN; i += blockDim.x) {
        unsigned char b = raw[i];
        if (b > 1) lgt1 = 1;
        if (b == 1 && (i & 3)) loneoff = 1;
        if (b == 0x3F && ((i & 3) == 1)) l3f1 = 1;
    }
    if (lgt1)    atomicOr(&fgt1, 1);
    if (loneoff) atomicOr(&foneoff, 1);
    if (l3f1)    atomicOr(&f3f1, 1);
    __syncthreads();
    int mode = fgt1 ? (f3f1 ? 3 : 2) : (foneoff ? 0 : 1);
    for (int i = tid; i < S_LEN; i += blockDim.x) {
        int v;
        if (mode == 0)      v = (raw[i] != 0);
        else if (mode == 1) v = (((const int*)raw)[i] != 0);
        else if (mode == 2) v = (((const float*)raw)[i] != 0.0f);
        else                v = (((const unsigned short*)raw)[i] != 0);
        g_smask[i] = v;
    }
    __syncthreads();

    int base = tid * 8;
    int loc[8];
    int cnt = 0;
    #pragma unroll
    for (int j = 0; j < 8; j++)
        if (g_smask[base + j]) loc[cnt++] = base + j;
    scan[tid] = cnt;
    __syncthreads();
    for (int off = 1; off < 256; off <<= 1) {
        int v = scan[tid];
        int add = (tid >= off) ? scan[tid - off] : 0;
        __syncthreads();
        scan[tid] = v + add;
        __syncthreads();
    }
    int total = scan[255];
    int start = scan[tid] - cnt;
    for (int j = 0; j < cnt; j++) g_sidx[start + j] = loc[j];
    int npad = ((total + 127) >> 7) << 7;
    if (npad == 0) npad = 128;
    if (tid == 0) g_npad = npad;
    __syncthreads();
    int fi = (total > 0) ? g_sidx[0] : 0;
    for (int i = total + tid; i < npad; i += 256) g_sidx[i] = fi;
}

// ---------------------------------------------------------------------------
// helpers for mma.sync path
// ---------------------------------------------------------------------------
__device__ __forceinline__ uint32_t smem_u32(const void* p) {
    uint32_t a;
    asm("{ .reg .u64 t; cvta.to.shared.u64 t, %1; cvt.u32.u64 %0, t; }" : "=r"(a) : "l"(p));
    return a;
}
#define LDM4(r0, r1, r2, r3, a)                                              \
    asm volatile("ldmatrix.sync.aligned.m8n8.x4.shared.b16 {%0,%1,%2,%3}, [%4];" \
        : "=r"(r0), "=r"(r1), "=r"(r2), "=r"(r3) : "r"(a))
#define MMA_BF16(d, a, b0v, b1v)                                             \
    asm volatile("mma.sync.aligned.m16n8k16.row.col.f32.bf16.bf16.f32 "      \
        "{%0,%1,%2,%3},{%4,%5,%6,%7},{%8,%9},{%0,%1,%2,%3};"                 \
        : "+f"((d)[0]), "+f"((d)[1]), "+f"((d)[2]), "+f"((d)[3])             \
        : "r"((a)[0]), "r"((a)[1]), "r"((a)[2]), "r"((a)[3]),                \
          "r"(b0v), "r"(b1v))

__device__ __forceinline__ void split_pack(float a, float b, uint32_t& hi, uint32_t& lo) {
    __nv_bfloat16 ha = __float2bfloat16(a), hb = __float2bfloat16(b);
    __nv_bfloat16 la = __float2bfloat16(a - __bfloat162float(ha));
    __nv_bfloat16 lb = __float2bfloat16(b - __bfloat162float(hb));
    __nv_bfloat162 h; h.x = ha; h.y = hb;
    __nv_bfloat162 l; l.x = la; l.y = lb;
    hi = *(uint32_t*)&h;
    lo = *(uint32_t*)&l;
}

// ---------------------------------------------------------------------------
// Split-bf16 mma.sync QKV GEMM over gathered spike rows, RoPE fused.
// CTA: 128(M gathered) x 128(N) x K=32 tiles. 8 warps (2 M x 4 N), warp 64x32.
// smem tiles: Ahi|Alo|Bhi|Blo, 128 rows x 80B (32 bf16 padded) each.
// Epilogue: acc -> smem (stride 132) -> RoPE -> coalesced scattered rows.
// ---------------------------------------------------------------------------
#define TILE_B   10240            // 128*80
#define OFF_AHI  0
#define OFF_ALO  10240
#define OFF_BHI  20480
#define OFF_BLO  30720
#define EPI_STRIDE 132
#define GEMM_SMEM  (128 * EPI_STRIDE * 4)   // 67584 >= 40960 tiles

__global__ __launch_bounds__(256) void qkv_mma_kernel(
    const float* __restrict__ x,
    const float* __restrict__ Wq,
    const float* __restrict__ Wk,
    const float* __restrict__ Wv)
{
    int s0 = blockIdx.x * 128;
    if (s0 >= g_npad) return;

    extern __shared__ char sm[];
    int bz = blockIdx.z;
    const float* Wm  = (bz == 0) ? Wq : (bz == 1) ? Wk : Wv;
    float*       outp = (bz == 0) ? g_Q : (bz == 1) ? g_K : g_V;
    int n0 = blockIdx.y * 128;

    int tid = threadIdx.x;
    int wid = tid >> 5, lane = tid & 31;
    int wm = wid & 1, wn = wid >> 1;          // warp M row / N col

    // loader mapping: thread owns (row, 16-float half of K-tile)
    int lrow = tid >> 1;
    int lks  = (tid & 1) * 16;
    int sA = g_sidx[s0 + lrow];
    const float* arow = x  + (size_t)sA * D_DIM + lks;
    const float* brow = Wm + (size_t)(n0 + lrow) * D_DIM + lks;
    uint32_t wrb = (uint32_t)lrow * 80 + (uint32_t)lks * 2;   // byte off in tile

    uint32_t smb = smem_u32(sm);
    // ldmatrix lane addresses (A: 16 rows x 16B cols; B: 8 rows x2 k-halves)
    uint32_t aHiAddr = smb + OFF_AHI + (uint32_t)(wm * 64 + (lane & 15)) * 80 + (uint32_t)(lane >> 4) * 16;
    uint32_t aLoAddr = aHiAddr + (OFF_ALO - OFF_AHI);
    uint32_t bRowOff = (uint32_t)(wn * 32 + ((lane >> 4) << 3) + (lane & 7)) * 80
                     + (uint32_t)((lane >> 3) & 1) * 16;
    uint32_t bHiAddr = smb + OFF_BHI + bRowOff;
    uint32_t bLoAddr = smb + OFF_BLO + bRowOff;

    float acc[4][4][4];
    #pragma unroll
    for (int i = 0; i < 4; i++)
        #pragma unroll
        for (int j = 0; j < 4; j++)
            #pragma unroll
            for (int r = 0; r < 4; r++) acc[i][j][r] = 0.f;

    for (int kt = 0; kt < D_DIM / 32; kt++) {
        int kb = kt * 32;
        __syncthreads();   // prior ldmatrix reads done before overwrite
        // load + split-convert A and B halves (16 floats each)
        #pragma unroll
        for (int q = 0; q < 4; q++) {
            float4 va = *(const float4*)(arow + kb + q * 4);
            uint32_t h0, l0, h1, l1;
            split_pack(va.x, va.y, h0, l0);
            split_pack(va.z, va.w, h1, l1);
            *(uint32_t*)(sm + OFF_AHI + wrb + q * 8)     = h0;
            *(uint32_t*)(sm + OFF_AHI + wrb + q * 8 + 4) = h1;
            *(uint32_t*)(sm + OFF_ALO + wrb + q * 8)     = l0;
            *(uint32_t*)(sm + OFF_ALO + wrb + q * 8 + 4) = l1;
            float4 vb = *(const float4*)(brow + kb + q * 4);
            split_pack(vb.x, vb.y, h0, l0);
            split_pack(vb.z, vb.w, h1, l1);
            *(uint32_t*)(sm + OFF_BHI + wrb + q * 8)     = h0;
            *(uint32_t*)(sm + OFF_BHI + wrb + q * 8 + 4) = h1;
            *(uint32_t*)(sm + OFF_BLO + wrb + q * 8)     = l0;
            *(uint32_t*)(sm + OFF_BLO + wrb + q * 8 + 4) = l1;
        }
        __syncthreads();

        #pragma unroll
        for (int ksub = 0; ksub < 2; ksub++) {
            uint32_t kbyte = ksub * 32;
            uint32_t aF[4][4], bH[8], bL[8];
            #pragma unroll
            for (int mf = 0; mf < 4; mf++)
                LDM4(aF[mf][0], aF[mf][1], aF[mf][2], aF[mf][3],
                     aHiAddr + mf * 1280 + kbyte);
            LDM4(bH[0], bH[1], bH[2], bH[3], bHiAddr + kbyte);          // frags 0,1
            LDM4(bH[4], bH[5], bH[6], bH[7], bHiAddr + 1280 + kbyte);   // frags 2,3
            #pragma unroll
            for (int mf = 0; mf < 4; mf++)
                #pragma unroll
                for (int nf = 0; nf < 4; nf++)
                    MMA_BF16(acc[mf][nf], aF[mf], bH[2*nf], bH[2*nf+1]);
            LDM4(bL[0], bL[1], bL[2], bL[3], bLoAddr + kbyte);
            LDM4(bL[4], bL[5], bL[6], bL[7], bLoAddr + 1280 + kbyte);
            #pragma unroll
            for (int mf = 0; mf < 4; mf++)
                #pragma unroll
                for (int nf = 0; nf < 4; nf++)
                    MMA_BF16(acc[mf][nf], aF[mf], bL[2*nf], bL[2*nf+1]);
            #pragma unroll
            for (int mf = 0; mf < 4; mf++)
                LDM4(aF[mf][0], aF[mf][1], aF[mf][2], aF[mf][3],
                     aLoAddr + mf * 1280 + kbyte);
            #pragma unroll
            for (int mf = 0; mf < 4; mf++)
                #pragma unroll
                for (int nf = 0; nf < 4; nf++)
                    MMA_BF16(acc[mf][nf], aF[mf], bH[2*nf], bH[2*nf+1]);
        }
    }

    // ---------------- epilogue: stage -> RoPE -> scattered coalesced rows ---
    __syncthreads();
    float* st = (float*)sm;
    #pragma unroll
    for (int mf = 0; mf < 4; mf++)
        #pragma unroll
        for (int nf = 0; nf < 4; nf++) {
            int r = wm * 64 + mf * 16 + (lane >> 2);
            int c = wn * 32 + nf * 8 + (lane & 3) * 2;
            st[r * EPI_STRIDE + c]           = acc[mf][nf][0];
            st[r * EPI_STRIDE + c + 1]       = acc[mf][nf][1];
            st[(r + 8) * EPI_STRIDE + c]     = acc[mf][nf][2];
            st[(r + 8) * EPI_STRIDE + c + 1] = acc[mf][nf][3];
        }
    __syncthreads();

    float invf = (float)exp(-(double)lane * 0.28782313662425575);  // ln(1e4)/32
    for (int t2 = 0; t2 < 32; t2++) {
        int r = wid * 16 + (t2 >> 1);
        int h = t2 & 1;
        int s = g_sidx[s0 + r];
        float a = st[r * EPI_STRIDE + h * 64 + lane];
        float b = st[r * EPI_STRIDE + h * 64 + 32 + lane];
        float* gp = outp + (size_t)s * D_DIM + n0 + h * 64;
        if (bz < 2) {
            float sn, cs;
            sincosf((float)s * invf, &sn, &cs);
            gp[lane]      = a * cs - b * sn;
            gp[lane + 32] = b * cs + a * sn;
        } else {
            gp[lane]      = a;
            gp[lane + 32] = b;
        }
    }
}

// ---------------------------------------------------------------------------
// Flash-style windowed attention (unchanged from passing R10 kernel).
// ---------------------------------------------------------------------------
__global__ __launch_bounds__(256) void attn_kernel(float* __restrict__ out) {
    extern __shared__ float asmem[];
    float (*Qs)[68] = (float (*)[68])(asmem);
    float (*Ks)[68] = (float (*)[68])(asmem + 1 * 64 * 68);
    float (*Vs)[68] = (float (*)[68])(asmem + 2 * 64 * 68);
    float (*Ps)[68] = (float (*)[68])(asmem + 3 * 64 * 68);
    int* smk = (int*)(asmem + 4 * 64 * 68);

    int q0 = blockIdx.x * 64;
    int h  = blockIdx.y;
    int tid = threadIdx.x;
    int tx = tid & 15, ty = tid >> 4;
    int row   = tid >> 2;
    int cbase = (tid & 3) << 4;

    {
        const float* qp = g_Q + (size_t)(q0 + row) * D_DIM + h * HD + cbase;
        #pragma unroll
        for (int t = 0; t < 4; t++) {
            float4 qv = *(const float4*)(qp + t * 4);
            int d = cbase + t * 4;
            Qs[d+0][row] = qv.x; Qs[d+1][row] = qv.y;
            Qs[d+2][row] = qv.z; Qs[d+3][row] = qv.w;
        }
    }

    float m_i[4], l_i[4], acc[4][4];
    #pragma unroll
    for (int i = 0; i < 4; i++) {
        m_i[i] = -1e30f; l_i[i] = 0.f;
        #pragma unroll
        for (int j = 0; j < 4; j++) acc[i][j] = 0.f;
    }

    int bx = blockIdx.x;
    int tlo = (bx > 8) ? (bx - 8) : 0;
    int nanchor = (tlo > 0) ? 1 : 0;
    int ntiles = nanchor + (bx - tlo + 1);

    for (int it = 0; it < ntiles; it++) {
        bool anchorOnly = (nanchor && it == 0);
        int kt = anchorOnly ? 0 : (tlo + it - nanchor);
        int k0 = kt * 64;
        __syncthreads();
        {
            const float* kp = g_K + (size_t)(k0 + row) * D_DIM + h * HD + cbase;
            const float* vp = g_V + (size_t)(k0 + row) * D_DIM + h * HD + cbase;
            #pragma unroll
            for (int t = 0; t < 4; t++) {
                float4 kv = *(const float4*)(kp + t * 4);
                int d = cbase + t * 4;
                Ks[d+0][row] = kv.x; Ks[d+1][row] = kv.y;
                Ks[d+2][row] = kv.z; Ks[d+3][row] = kv.w;
                *(float4*)&Vs[row][d] = *(const float4*)(vp + t * 4);
            }
            if (tid < 64) smk[tid] = g_smask[k0 + tid];
        }
        __syncthreads();

        float sc[4][4];
        #pragma unroll
        for (int i = 0; i < 4; i++)
            #pragma unroll
            for (int j = 0; j < 4; j++) sc[i][j] = 0.f;
        #pragma unroll
        for (int d = 0; d < 64; d++) {
            float4 qq = *(const float4*)&Qs[d][ty * 4];
            float4 kk = *(const float4*)&Ks[d][tx * 4];
            float qa[4] = {qq.x, qq.y, qq.z, qq.w};
            float ka[4] = {kk.x, kk.y, kk.z, kk.w};
            #pragma unroll
            for (int i = 0; i < 4; i++)
                #pragma unroll
                for (int j = 0; j < 4; j++)
                    sc[i][j] = fmaf(qa[i], ka[j], sc[i][j]);
        }

        #pragma unroll
        for (int i = 0; i < 4; i++) {
            int q = q0 + ty * 4 + i;
            float sv[4];
            float mt = -1e30f;
            #pragma unroll
            for (int j = 0; j < 4; j++) {
                int k = k0 + tx * 4 + j;
                int dist = q - k;
                bool ok = (dist >= 0) && smk[tx * 4 + j] &&
                          ((k < 4) || (!anchorOnly && dist <= WND));
                float sx = sc[i][j] * 0.125f;
                sv[j] = ok ? sx : -1e30f;
                mt = fmaxf(mt, sv[j]);
            }
            #pragma unroll
            for (int o = 8; o > 0; o >>= 1)
                mt = fmaxf(mt, __shfl_xor_sync(0xffffffffu, mt, o));
            float mn = fmaxf(m_i[i], mt);
            float alpha = expf(m_i[i] - mn);
            m_i[i] = mn;
            float p[4], rs = 0.f;
            #pragma unroll
            for (int j = 0; j < 4; j++) {
                p[j] = (sv[j] > -1e29f) ? expf(sv[j] - mn) : 0.f;
                rs += p[j];
            }
            #pragma unroll
            for (int o = 8; o > 0; o >>= 1)
                rs += __shfl_xor_sync(0xffffffffu, rs, o);
            l_i[i] = l_i[i] * alpha + rs;
            #pragma unroll
            for (int j = 0; j < 4; j++) acc[i][j] *= alpha;
            *(float4*)&Ps[ty * 4 + i][tx * 4] = make_float4(p[0], p[1], p[2], p[3]);
        }
        __syncthreads();

        #pragma unroll 4
        for (int k = 0; k < 64; k++) {
            float4 vv = *(const float4*)&Vs[k][tx * 4];
            #pragma unroll
            for (int i = 0; i < 4; i++) {
                float pw = Ps[ty * 4 + i][k];
                acc[i][0] = fmaf(pw, vv.x, acc[i][0]);
                acc[i][1] = fmaf(pw, vv.y, acc[i][1]);
                acc[i][2] = fmaf(pw, vv.z, acc[i][2]);
                acc[i][3] = fmaf(pw, vv.w, acc[i][3]);
            }
        }
    }

    #pragma unroll
    for (int i = 0; i < 4; i++) {
        int q = q0 + ty * 4 + i;
        float mult = (l_i[i] > 0.f && g_smask[q]) ? (1.f / l_i[i]) : 0.f;
        float4 o4 = make_float4(acc[i][0] * mult, acc[i][1] * mult,
                                acc[i][2] * mult, acc[i][3] * mult);
        *(float4*)&out[(size_t)q * D_DIM + h * HD + tx * 4] = o4;
    }
}

// ---------------------------------------------------------------------------
extern "C" void kernel_launch(void* const* d_in, const int* in_sizes, int n_in,
                              void* d_out, int out_size) {
    const float* x          = (const float*)d_in[0];
    const unsigned char* mk = (const unsigned char*)d_in[1];
    const float* Wq         = (const float*)d_in[2];
    const float* Wk         = (const float*)d_in[3];
    const float* Wv         = (const float*)d_in[4];
    float* out = (float*)d_out;

    prep_mask_kernel<<<1, 256>>>(mk);

    cudaFuncSetAttribute(qkv_mma_kernel, cudaFuncAttributeMaxDynamicSharedMemorySize, GEMM_SMEM);
    qkv_mma_kernel<<<dim3(16, D_DIM / 128, 3), 256, GEMM_SMEM>>>(x, Wq, Wk, Wv);

    const int ATTN_SMEM = (4 * 64 * 68 + 64) * 4;
    cudaFuncSetAttribute(attn_kernel, cudaFuncAttributeMaxDynamicSharedMemorySize, ATTN_SMEM);
    attn_kernel<<<dim3(S_LEN / 64, N_HEADS), 256, ATTN_SMEM>>>(out);
}

// round 16
// speedup vs baseline: 3.6458x; 1.7498x over previous
#include <cuda_runtime.h>
#include <cuda_bf16.h>
#include <cstdint>
#include <math.h>

#define S_LEN  2048
#define D_DIM  1536
#define N_HEADS 24
#define HD      64
#define WND    512

// Scratch (device globals: no allocations allowed)
__device__ float g_Q[S_LEN * D_DIM];
__device__ float g_K[S_LEN * D_DIM];
__device__ float g_V[S_LEN * D_DIM];
__device__ int   g_smask[S_LEN];
__device__ int   g_sidx[S_LEN + 128];
__device__ int   g_npad;
__device__ int   g_ntot;

// ---------------------------------------------------------------------------
// spike_mask dtype detection + normalization + spike-index compaction.
// ---------------------------------------------------------------------------
__global__ void prep_mask_kernel(const unsigned char* __restrict__ raw) {
    __shared__ int fgt1, foneoff, f3f1;
    __shared__ int scan[256];
    int tid = threadIdx.x;
    if (tid == 0) { fgt1 = 0; foneoff = 0; f3f1 = 0; }
    __syncthreads();
    int lgt1 = 0, loneoff = 0, l3f1 = 0;
    for (int i = tid; i < S_LEN; i += blockDim.x) {
        unsigned char b = raw[i];
        if (b > 1) lgt1 = 1;
        if (b == 1 && (i & 3)) loneoff = 1;
        if (b == 0x3F && ((i & 3) == 1)) l3f1 = 1;
    }
    if (lgt1)    atomicOr(&fgt1, 1);
    if (loneoff) atomicOr(&foneoff, 1);
    if (l3f1)    atomicOr(&f3f1, 1);
    __syncthreads();
    int mode = fgt1 ? (f3f1 ? 3 : 2) : (foneoff ? 0 : 1);
    for (int i = tid; i < S_LEN; i += blockDim.x) {
        int v;
        if (mode == 0)      v = (raw[i] != 0);
        else if (mode == 1) v = (((const int*)raw)[i] != 0);
        else if (mode == 2) v = (((const float*)raw)[i] != 0.0f);
        else                v = (((const unsigned short*)raw)[i] != 0);
        g_smask[i] = v;
    }
    __syncthreads();

    int base = tid * 8;
    int loc[8];
    int cnt = 0;
    #pragma unroll
    for (int j = 0; j < 8; j++)
        if (g_smask[base + j]) loc[cnt++] = base + j;
    scan[tid] = cnt;
    __syncthreads();
    for (int off = 1; off < 256; off <<= 1) {
        int v = scan[tid];
        int add = (tid >= off) ? scan[tid - off] : 0;
        __syncthreads();
        scan[tid] = v + add;
        __syncthreads();
    }
    int total = scan[255];
    int start = scan[tid] - cnt;
    for (int j = 0; j < cnt; j++) g_sidx[start + j] = loc[j];
    int npad = ((total + 127) >> 7) << 7;
    if (npad == 0) npad = 128;
    if (tid == 0) { g_npad = npad; g_ntot = total; }
    __syncthreads();
    int fi = (total > 0) ? g_sidx[0] : 0;
    for (int i = total + tid; i < npad; i += 256) g_sidx[i] = fi;
}

// ---------------------------------------------------------------------------
// zero-fill output (d_out is poisoned; compacted attention writes spike rows only)
// ---------------------------------------------------------------------------
__global__ void zero_out_kernel(float4* __restrict__ o) {
    const int n4 = S_LEN * D_DIM / 4;
    int stride = gridDim.x * blockDim.x;
    float4 z = make_float4(0.f, 0.f, 0.f, 0.f);
    for (int i = blockIdx.x * blockDim.x + threadIdx.x; i < n4; i += stride)
        o[i] = z;
}

// ---------------------------------------------------------------------------
// helpers for mma.sync path
// ---------------------------------------------------------------------------
__device__ __forceinline__ uint32_t smem_u32(const void* p) {
    uint32_t a;
    asm("{ .reg .u64 t; cvta.to.shared.u64 t, %1; cvt.u32.u64 %0, t; }" : "=r"(a) : "l"(p));
    return a;
}
#define LDM4(r0, r1, r2, r3, a)                                              \
    asm volatile("ldmatrix.sync.aligned.m8n8.x4.shared.b16 {%0,%1,%2,%3}, [%4];" \
        : "=r"(r0), "=r"(r1), "=r"(r2), "=r"(r3) : "r"(a))
#define MMA_BF16(d, a, b0v, b1v)                                             \
    asm volatile("mma.sync.aligned.m16n8k16.row.col.f32.bf16.bf16.f32 "      \
        "{%0,%1,%2,%3},{%4,%5,%6,%7},{%8,%9},{%0,%1,%2,%3};"                 \
        : "+f"((d)[0]), "+f"((d)[1]), "+f"((d)[2]), "+f"((d)[3])             \
        : "r"((a)[0]), "r"((a)[1]), "r"((a)[2]), "r"((a)[3]),                \
          "r"(b0v), "r"(b1v))

__device__ __forceinline__ void split_pack(float a, float b, uint32_t& hi, uint32_t& lo) {
    __nv_bfloat16 ha = __float2bfloat16(a), hb = __float2bfloat16(b);
    __nv_bfloat16 la = __float2bfloat16(a - __bfloat162float(ha));
    __nv_bfloat16 lb = __float2bfloat16(b - __bfloat162float(hb));
    __nv_bfloat162 h; h.x = ha; h.y = hb;
    __nv_bfloat162 l; l.x = la; l.y = lb;
    hi = *(uint32_t*)&h;
    lo = *(uint32_t*)&l;
}

// ---------------------------------------------------------------------------
// Split-bf16 mma.sync QKV GEMM over gathered spike rows, RoPE fused.
// (unchanged from passing R11 kernel)
// ---------------------------------------------------------------------------
#define OFF_AHI  0
#define OFF_ALO  10240
#define OFF_BHI  20480
#define OFF_BLO  30720
#define EPI_STRIDE 132
#define GEMM_SMEM  (128 * EPI_STRIDE * 4)

__global__ __launch_bounds__(256) void qkv_mma_kernel(
    const float* __restrict__ x,
    const float* __restrict__ Wq,
    const float* __restrict__ Wk,
    const float* __restrict__ Wv)
{
    int s0 = blockIdx.x * 128;
    if (s0 >= g_npad) return;

    extern __shared__ char sm[];
    int bz = blockIdx.z;
    const float* Wm  = (bz == 0) ? Wq : (bz == 1) ? Wk : Wv;
    float*       outp = (bz == 0) ? g_Q : (bz == 1) ? g_K : g_V;
    int n0 = blockIdx.y * 128;

    int tid = threadIdx.x;
    int wid = tid >> 5, lane = tid & 31;
    int wm = wid & 1, wn = wid >> 1;

    int lrow = tid >> 1;
    int lks  = (tid & 1) * 16;
    int sA = g_sidx[s0 + lrow];
    const float* arow = x  + (size_t)sA * D_DIM + lks;
    const float* brow = Wm + (size_t)(n0 + lrow) * D_DIM + lks;
    uint32_t wrb = (uint32_t)lrow * 80 + (uint32_t)lks * 2;

    uint32_t smb = smem_u32(sm);
    uint32_t aHiAddr = smb + OFF_AHI + (uint32_t)(wm * 64 + (lane & 15)) * 80 + (uint32_t)(lane >> 4) * 16;
    uint32_t aLoAddr = aHiAddr + (OFF_ALO - OFF_AHI);
    uint32_t bRowOff = (uint32_t)(wn * 32 + ((lane >> 4) << 3) + (lane & 7)) * 80
                     + (uint32_t)((lane >> 3) & 1) * 16;
    uint32_t bHiAddr = smb + OFF_BHI + bRowOff;
    uint32_t bLoAddr = smb + OFF_BLO + bRowOff;

    float acc[4][4][4];
    #pragma unroll
    for (int i = 0; i < 4; i++)
        #pragma unroll
        for (int j = 0; j < 4; j++)
            #pragma unroll
            for (int r = 0; r < 4; r++) acc[i][j][r] = 0.f;

    for (int kt = 0; kt < D_DIM / 32; kt++) {
        int kb = kt * 32;
        __syncthreads();
        #pragma unroll
        for (int q = 0; q < 4; q++) {
            float4 va = *(const float4*)(arow + kb + q * 4);
            uint32_t h0, l0, h1, l1;
            split_pack(va.x, va.y, h0, l0);
            split_pack(va.z, va.w, h1, l1);
            *(uint32_t*)(sm + OFF_AHI + wrb + q * 8)     = h0;
            *(uint32_t*)(sm + OFF_AHI + wrb + q * 8 + 4) = h1;
            *(uint32_t*)(sm + OFF_ALO + wrb + q * 8)     = l0;
            *(uint32_t*)(sm + OFF_ALO + wrb + q * 8 + 4) = l1;
            float4 vb = *(const float4*)(brow + kb + q * 4);
            split_pack(vb.x, vb.y, h0, l0);
            split_pack(vb.z, vb.w, h1, l1);
            *(uint32_t*)(sm + OFF_BHI + wrb + q * 8)     = h0;
            *(uint32_t*)(sm + OFF_BHI + wrb + q * 8 + 4) = h1;
            *(uint32_t*)(sm + OFF_BLO + wrb + q * 8)     = l0;
            *(uint32_t*)(sm + OFF_BLO + wrb + q * 8 + 4) = l1;
        }
        __syncthreads();

        #pragma unroll
        for (int ksub = 0; ksub < 2; ksub++) {
            uint32_t kbyte = ksub * 32;
            uint32_t aF[4][4], bH[8], bL[8];
            #pragma unroll
            for (int mf = 0; mf < 4; mf++)
                LDM4(aF[mf][0], aF[mf][1], aF[mf][2], aF[mf][3],
                     aHiAddr + mf * 1280 + kbyte);
            LDM4(bH[0], bH[1], bH[2], bH[3], bHiAddr + kbyte);
            LDM4(bH[4], bH[5], bH[6], bH[7], bHiAddr + 1280 + kbyte);
            #pragma unroll
            for (int mf = 0; mf < 4; mf++)
                #pragma unroll
                for (int nf = 0; nf < 4; nf++)
                    MMA_BF16(acc[mf][nf], aF[mf], bH[2*nf], bH[2*nf+1]);
            LDM4(bL[0], bL[1], bL[2], bL[3], bLoAddr + kbyte);
            LDM4(bL[4], bL[5], bL[6], bL[7], bLoAddr + 1280 + kbyte);
            #pragma unroll
            for (int mf = 0; mf < 4; mf++)
                #pragma unroll
                for (int nf = 0; nf < 4; nf++)
                    MMA_BF16(acc[mf][nf], aF[mf], bL[2*nf], bL[2*nf+1]);
            #pragma unroll
            for (int mf = 0; mf < 4; mf++)
                LDM4(aF[mf][0], aF[mf][1], aF[mf][2], aF[mf][3],
                     aLoAddr + mf * 1280 + kbyte);
            #pragma unroll
            for (int mf = 0; mf < 4; mf++)
                #pragma unroll
                for (int nf = 0; nf < 4; nf++)
                    MMA_BF16(acc[mf][nf], aF[mf], bH[2*nf], bH[2*nf+1]);
        }
    }

    __syncthreads();
    float* st = (float*)sm;
    #pragma unroll
    for (int mf = 0; mf < 4; mf++)
        #pragma unroll
        for (int nf = 0; nf < 4; nf++) {
            int r = wm * 64 + mf * 16 + (lane >> 2);
            int c = wn * 32 + nf * 8 + (lane & 3) * 2;
            st[r * EPI_STRIDE + c]           = acc[mf][nf][0];
            st[r * EPI_STRIDE + c + 1]       = acc[mf][nf][1];
            st[(r + 8) * EPI_STRIDE + c]     = acc[mf][nf][2];
            st[(r + 8) * EPI_STRIDE + c + 1] = acc[mf][nf][3];
        }
    __syncthreads();

    float invf = (float)exp(-(double)lane * 0.28782313662425575);
    for (int t2 = 0; t2 < 32; t2++) {
        int r = wid * 16 + (t2 >> 1);
        int h = t2 & 1;
        int s = g_sidx[s0 + r];
        float a = st[r * EPI_STRIDE + h * 64 + lane];
        float b = st[r * EPI_STRIDE + h * 64 + 32 + lane];
        float* gp = outp + (size_t)s * D_DIM + n0 + h * 64;
        if (bz < 2) {
            float sn, cs;
            sincosf((float)s * invf, &sn, &cs);
            gp[lane]      = a * cs - b * sn;
            gp[lane + 32] = b * cs + a * sn;
        } else {
            gp[lane]      = a;
            gp[lane + 32] = b;
        }
    }
}

// ---------------------------------------------------------------------------
// Compacted flash attention: queries AND keys iterate over spike rows only.
// g_sidx sorted => causality is (sj <= si). Window start found by binary
// search; anchors (orig pos < 4) live in compacted tile 0.
// ---------------------------------------------------------------------------
__global__ __launch_bounds__(256) void attn_kernel(float* __restrict__ out) {
    extern __shared__ float asmem[];
    float (*Qs)[68] = (float (*)[68])(asmem);
    float (*Ks)[68] = (float (*)[68])(asmem + 1 * 64 * 68);
    float (*Vs)[68] = (float (*)[68])(asmem + 2 * 64 * 68);
    float (*Ps)[68] = (float (*)[68])(asmem + 3 * 64 * 68);
    int* sQ  = (int*)(asmem + 4 * 64 * 68);        // 64 query orig positions
    int* sK  = sQ + 64;                            // 64 key orig positions
    int* shJ = sK + 64;                            // [0] = jmin

    int q0c = blockIdx.x * 64;
    if (q0c >= g_npad) return;
    int total = g_ntot;
    int h  = blockIdx.y;
    int tid = threadIdx.x;
    int tx = tid & 15, ty = tid >> 4;
    int row   = tid >> 2;
    int cbase = (tid & 3) << 4;

    if (tid < 64) sQ[tid] = g_sidx[q0c + tid];
    if (tid == 0) {
        // lower_bound over g_sidx[0..q0c] for (g_sidx[q0c] - WND)
        int v = g_sidx[q0c] - WND;
        int lo = 0, hi = q0c;
        while (lo < hi) {
            int mid = (lo + hi) >> 1;
            if (g_sidx[mid] < v) lo = mid + 1; else hi = mid;
        }
        shJ[0] = lo;
    }

    {   // load Q tile transposed (gathered rows)
        const float* qp = g_Q + (size_t)g_sidx[q0c + row] * D_DIM + h * HD + cbase;
        #pragma unroll
        for (int t = 0; t < 4; t++) {
            float4 qv = *(const float4*)(qp + t * 4);
            int d = cbase + t * 4;
            Qs[d+0][row] = qv.x; Qs[d+1][row] = qv.y;
            Qs[d+2][row] = qv.z; Qs[d+3][row] = qv.w;
        }
    }
    __syncthreads();

    int si[4];
    #pragma unroll
    for (int i = 0; i < 4; i++) si[i] = sQ[ty * 4 + i];

    float m_i[4], l_i[4], acc[4][4];
    #pragma unroll
    for (int i = 0; i < 4; i++) {
        m_i[i] = -1e30f; l_i[i] = 0.f;
        #pragma unroll
        for (int j = 0; j < 4; j++) acc[i][j] = 0.f;
    }

    int bxc = q0c >> 6;
    int tloC = shJ[0] >> 6;
    int nanchor = (tloC > 0) ? 1 : 0;
    int ntiles = nanchor + (bxc - tloC + 1);

    for (int it = 0; it < ntiles; it++) {
        bool anchorOnly = (nanchor && it == 0);
        int kt = anchorOnly ? 0 : (tloC + it - nanchor);
        int k0c = kt * 64;
        __syncthreads();
        {
            int kg = k0c + row;
            const float* kp = g_K + (size_t)g_sidx[kg] * D_DIM + h * HD + cbase;
            const float* vp = g_V + (size_t)g_sidx[kg] * D_DIM + h * HD + cbase;
            #pragma unroll
            for (int t = 0; t < 4; t++) {
                float4 kv = *(const float4*)(kp + t * 4);
                int d = cbase + t * 4;
                Ks[d+0][row] = kv.x; Ks[d+1][row] = kv.y;
                Ks[d+2][row] = kv.z; Ks[d+3][row] = kv.w;
                *(float4*)&Vs[row][d] = *(const float4*)(vp + t * 4);
            }
            if (tid < 64) {
                int kk = k0c + tid;
                sK[tid] = (kk < total) ? g_sidx[kk] : 0x7FFFFFFF;
            }
        }
        __syncthreads();

        float sc[4][4];
        #pragma unroll
        for (int i = 0; i < 4; i++)
            #pragma unroll
            for (int j = 0; j < 4; j++) sc[i][j] = 0.f;
        #pragma unroll
        for (int d = 0; d < 64; d++) {
            float4 qq = *(const float4*)&Qs[d][ty * 4];
            float4 kk = *(const float4*)&Ks[d][tx * 4];
            float qa[4] = {qq.x, qq.y, qq.z, qq.w};
            float ka[4] = {kk.x, kk.y, kk.z, kk.w};
            #pragma unroll
            for (int i = 0; i < 4; i++)
                #pragma unroll
                for (int j = 0; j < 4; j++)
                    sc[i][j] = fmaf(qa[i], ka[j], sc[i][j]);
        }

        int sjv[4];
        #pragma unroll
        for (int j = 0; j < 4; j++) sjv[j] = sK[tx * 4 + j];

        #pragma unroll
        for (int i = 0; i < 4; i++) {
            float sv[4];
            float mt = -1e30f;
            #pragma unroll
            for (int j = 0; j < 4; j++) {
                int sj = sjv[j];
                bool ok = (sj <= si[i]) &&
                          ((sj < 4) || (!anchorOnly && (si[i] - sj) <= WND));
                float sx = sc[i][j] * 0.125f;
                sv[j] = ok ? sx : -1e30f;
                mt = fmaxf(mt, sv[j]);
            }
            #pragma unroll
            for (int o = 8; o > 0; o >>= 1)
                mt = fmaxf(mt, __shfl_xor_sync(0xffffffffu, mt, o));
            float mn = fmaxf(m_i[i], mt);
            float alpha = expf(m_i[i] - mn);
            m_i[i] = mn;
            float p[4], rs = 0.f;
            #pragma unroll
            for (int j = 0; j < 4; j++) {
                p[j] = (sv[j] > -1e29f) ? expf(sv[j] - mn) : 0.f;
                rs += p[j];
            }
            #pragma unroll
            for (int o = 8; o > 0; o >>= 1)
                rs += __shfl_xor_sync(0xffffffffu, rs, o);
            l_i[i] = l_i[i] * alpha + rs;
            #pragma unroll
            for (int j = 0; j < 4; j++) acc[i][j] *= alpha;
            *(float4*)&Ps[ty * 4 + i][tx * 4] = make_float4(p[0], p[1], p[2], p[3]);
        }
        __syncthreads();

        #pragma unroll 4
        for (int k = 0; k < 64; k++) {
            float4 vv = *(const float4*)&Vs[k][tx * 4];
            #pragma unroll
            for (int i = 0; i < 4; i++) {
                float pw = Ps[ty * 4 + i][k];
                acc[i][0] = fmaf(pw, vv.x, acc[i][0]);
                acc[i][1] = fmaf(pw, vv.y, acc[i][1]);
                acc[i][2] = fmaf(pw, vv.z, acc[i][2]);
                acc[i][3] = fmaf(pw, vv.w, acc[i][3]);
            }
        }
    }

    // epilogue: scatter to original rows; skip padded queries (avoid clobber)
    #pragma unroll
    for (int i = 0; i < 4; i++) {
        int ig = q0c + ty * 4 + i;
        if (ig >= total) continue;
        float mult = (l_i[i] > 0.f) ? (1.f / l_i[i]) : 0.f;
        float4 o4 = make_float4(acc[i][0] * mult, acc[i][1] * mult,
                                acc[i][2] * mult, acc[i][3] * mult);
        *(float4*)&out[(size_t)si[i] * D_DIM + h * HD + tx * 4] = o4;
    }
}

// ---------------------------------------------------------------------------
extern "C" void kernel_launch(void* const* d_in, const int* in_sizes, int n_in,
                              void* d_out, int out_size) {
    const float* x          = (const float*)d_in[0];
    const unsigned char* mk = (const unsigned char*)d_in[1];
    const float* Wq         = (const float*)d_in[2];
    const float* Wk         = (const float*)d_in[3];
    const float* Wv         = (const float*)d_in[4];
    float* out = (float*)d_out;

    prep_mask_kernel<<<1, 256>>>(mk);
    zero_out_kernel<<<264, 256>>>((float4*)out);

    cudaFuncSetAttribute(qkv_mma_kernel, cudaFuncAttributeMaxDynamicSharedMemorySize, GEMM_SMEM);
    qkv_mma_kernel<<<dim3(16, D_DIM / 128, 3), 256, GEMM_SMEM>>>(x, Wq, Wk, Wv);

    const int ATTN_SMEM = (4 * 64 * 68 + 132) * 4;
    cudaFuncSetAttribute(attn_kernel, cudaFuncAttributeMaxDynamicSharedMemorySize, ATTN_SMEM);
    attn_kernel<<<dim3(S_LEN / 64, N_HEADS), 256, ATTN_SMEM>>>(out);
}